// round 14
// baseline (speedup 1.0000x reference)
#include <cuda_runtime.h>
#include <cuda_bf16.h>
#include <cuda_fp16.h>
#include <cstdint>

// ---------------------------------------------------------------------------
// out = sigmoid(BN( A @ M )),  A (65536 x 512) fp16 built from x, M (512x768)
// pre-combined.  GEMM: fp16 mma.sync m16n8k16, CTA 128x128, KB=64, 3-stage
// cp.async pipeline (unrolled, early issue), XOR-swizzled smem, BN partials
// fused in epilogue.  R14: warp layout 2Mx4N/64x32 -> 2Mx2N/64x64 (4 warps,
// 2 CTAs/SM): smem fragment traffic -33% (L1 was 69% vs tensor 59%).
// ---------------------------------------------------------------------------

#define NROWS   65536
#define DIN     768
#define KDIM    512
#define EDIM    768

#define KB      64          // K per stage
#define NITER   (KDIM / KB) // 8

#define TERMB   16384
#define STG     32768
#define SMEMB   (3 * STG)   // 98304

#define NSPLIT  4           // prep_B split-K factor
#define JCHUNK  (1536 / NSPLIT)

// __device__ scratch (allocation-free rule)
__device__ __align__(16) float   g_Mp[NSPLIT * KDIM * EDIM];   // split-K partials
__device__ __align__(16) __half  g_Bf[EDIM * KDIM];            // [e][k]
__device__ __align__(16) __half  g_Af[(size_t)NROWS * KDIM];   // [n][k]
__device__ __align__(16) __half  g_raw[(size_t)NROWS * EDIM];  // fp16 raw out
__device__ __align__(16) float   g_psum[EDIM * 512];           // [col][rowblk]
__device__ __align__(16) float   g_psqs[EDIM * 512];
__device__ __align__(16) float   g_scale[EDIM];
__device__ __align__(16) float   g_shift[EDIM];

// ---------------- PTX helpers (baseline sm_80+ features only) ---------------
__device__ __forceinline__ uint32_t smem_u32(const void* p) {
    uint32_t a;
    asm("{ .reg .u64 t; cvta.to.shared.u64 t, %1; cvt.u32.u64 %0, t; }" : "=r"(a) : "l"(p));
    return a;
}
__device__ __forceinline__ void cp16(uint32_t dst, const void* src) {
    asm volatile("cp.async.cg.shared.global [%0], [%1], 16;" :: "r"(dst), "l"(src) : "memory");
}
__device__ __forceinline__ void ldsm4(uint32_t* r, uint32_t a) {
    asm volatile("ldmatrix.sync.aligned.m8n8.x4.shared.b16 {%0,%1,%2,%3}, [%4];"
                 : "=r"(r[0]), "=r"(r[1]), "=r"(r[2]), "=r"(r[3]) : "r"(a));
}
__device__ __forceinline__ void mma_f16(float* c, const uint32_t* a,
                                        uint32_t b0, uint32_t b1) {
    asm volatile(
        "mma.sync.aligned.m16n8k16.row.col.f32.f16.f16.f32 "
        "{%0,%1,%2,%3}, {%4,%5,%6,%7}, {%8,%9}, {%0,%1,%2,%3};"
        : "+f"(c[0]), "+f"(c[1]), "+f"(c[2]), "+f"(c[3])
        : "r"(a[0]), "r"(a[1]), "r"(a[2]), "r"(a[3]), "r"(b0), "r"(b1));
}

// ---------------------------------------------------------------------------
// K0a: split-K weight prep.   [proven]
// ---------------------------------------------------------------------------
__global__ void __launch_bounds__(256) prep_B_partial(const float* __restrict__ w1a,
                                                      const float* __restrict__ w2a,
                                                      const float* __restrict__ w1b,
                                                      const float* __restrict__ w2b) {
    __shared__ __align__(16) float As[16][64];
    __shared__ __align__(16) float Bs[16][64];
    const int e0 = blockIdx.x * 64;
    const int i0 = blockIdx.y * 64;
    const int jz = blockIdx.z * JCHUNK;
    const int t  = threadIdx.x;
    const int tx = t & 15;
    const int ty = t >> 4;
    float acc[4][4] = {};

    for (int j0 = jz; j0 < jz + JCHUNK; j0 += 16) {
        {
            int r  = t >> 2;
            int jq = (t & 3) * 4;
            int i  = i0 + r;
            int j  = j0 + jq;
            float4 v;
            if (j < 768) {
                if (i < 256) {
                    v = *(const float4*)&w2a[(size_t)i * 768 + j];
                } else {
                    float4 a = *(const float4*)&w1a[(size_t)(i - 256) * 768 + j];
                    v = make_float4(0.5f * a.x, 0.5f * a.y, 0.5f * a.z, 0.5f * a.w);
                }
            } else {
                int jj = j - 768;
                if (i < 256) {
                    float4 a = *(const float4*)&w1a[(size_t)i * 768 + jj];
                    v = make_float4(0.5f * a.x, 0.5f * a.y, 0.5f * a.z, 0.5f * a.w);
                } else {
                    float4 a = *(const float4*)&w2a[(size_t)(i - 256) * 768 + jj];
                    float4 b = *(const float4*)&w1a[(size_t)(i - 256) * 768 + jj];
                    v = make_float4(fmaf(0.25f, b.x, 0.5f * a.x),
                                    fmaf(0.25f, b.y, 0.5f * a.y),
                                    fmaf(0.25f, b.z, 0.5f * a.z),
                                    fmaf(0.25f, b.w, 0.5f * a.w));
                }
            }
            As[jq + 0][r] = v.x; As[jq + 1][r] = v.y;
            As[jq + 2][r] = v.z; As[jq + 3][r] = v.w;
        }
        {
            int k  = t >> 4;
            int eq = (t & 15) * 4;
            int j  = j0 + k;
            const float* src = (j < 768) ? (w2b + (size_t)j * 768)
                                         : (w1b + (size_t)(j - 768) * 768);
            *(float4*)&Bs[k][eq] = *(const float4*)(src + e0 + eq);
        }
        __syncthreads();
        #pragma unroll
        for (int k = 0; k < 16; ++k) {
            float4 a = *(const float4*)&As[k][ty * 4];
            float4 b = *(const float4*)&Bs[k][tx * 4];
            float av[4] = {a.x, a.y, a.z, a.w};
            float bv[4] = {b.x, b.y, b.z, b.w};
            #pragma unroll
            for (int i = 0; i < 4; ++i)
                #pragma unroll
                for (int j = 0; j < 4; ++j)
                    acc[i][j] = fmaf(av[i], bv[j], acc[i][j]);
        }
        __syncthreads();
    }
    float* dst = g_Mp + (size_t)blockIdx.z * KDIM * EDIM;
    #pragma unroll
    for (int i = 0; i < 4; ++i)
        *(float4*)&dst[(size_t)(i0 + ty * 4 + i) * EDIM + e0 + tx * 4] =
            make_float4(acc[i][0], acc[i][1], acc[i][2], acc[i][3]);
}

// ---------------------------------------------------------------------------
// K0b: reduce split-K partials -> g_Bf = fp16(M^T)   [proven]
// ---------------------------------------------------------------------------
__global__ void __launch_bounds__(256) prep_B_reduce() {
    int idx = blockIdx.x * 256 + threadIdx.x;        // 512*768
    int k = idx / EDIM;
    int e = idx % EDIM;
    float s = g_Mp[idx];
    #pragma unroll
    for (int z = 1; z < NSPLIT; ++z)
        s += g_Mp[(size_t)z * KDIM * EDIM + idx];
    g_Bf[(size_t)e * KDIM + k] = __float2half_rn(s);
}

// ---------------------------------------------------------------------------
// K1: x -> g_Af (fp16)   [proven, at DRAM floor]
// ---------------------------------------------------------------------------
__global__ void __launch_bounds__(256) conv_A(const float* __restrict__ X) {
    int id = blockIdx.x * 256 + threadIdx.x;        // NROWS*64 threads
    int n  = id >> 6;
    int k  = (id & 63) * 8;
    const float* p = X + (size_t)n * DIN + k;
    float4 v0 = *(const float4*)p;
    float4 v1 = *(const float4*)(p + 4);
    if (k >= 256) {
        float4 w0 = *(const float4*)(p + 256);
        float4 w1 = *(const float4*)(p + 260);
        v0.x += w0.x; v0.y += w0.y; v0.z += w0.z; v0.w += w0.w;
        v1.x += w1.x; v1.y += w1.y; v1.z += w1.z; v1.w += w1.w;
    }
    __half2 h0 = __float22half2_rn(make_float2(v0.x, v0.y));
    __half2 h1 = __float22half2_rn(make_float2(v0.z, v0.w));
    __half2 h2 = __float22half2_rn(make_float2(v1.x, v1.y));
    __half2 h3 = __float22half2_rn(make_float2(v1.z, v1.w));
    uint4 o;
    o.x = *(uint32_t*)&h0; o.y = *(uint32_t*)&h1;
    o.z = *(uint32_t*)&h2; o.w = *(uint32_t*)&h3;
    *(uint4*)(g_Af + (size_t)n * KDIM + k) = o;
}

// ---------------------------------------------------------------------------
// K2: main GEMM via fp16 mma.sync + fused BN partials.  grid (6, 512),
// 128 threads (4 warps, 2Mx2N, warp tile 64x64), 2 CTAs/SM.
// ---------------------------------------------------------------------------
__device__ __forceinline__ void stage_issue(uint32_t st, int t, int n0, int e0, int k0) {
    #pragma unroll
    for (int j = 0; j < 16; ++j) {
        int idx  = t + 128 * j;          // 0..2047
        int part = idx >> 10;            // 0: A, 1: B
        int rr   = (idx >> 3) & 127;
        int c    = idx & 7;
        uint32_t dst = st + (uint32_t)(part * TERMB + rr * 128 + ((c ^ (rr & 7)) << 4));
        const __half* g = part ? g_Bf : g_Af;
        int base = part ? e0 : n0;
        cp16(dst, g + (size_t)(base + rr) * KDIM + k0 + c * 8);
    }
    asm volatile("cp.async.commit_group;" ::: "memory");
}

__global__ void __launch_bounds__(128, 2) gemm_mma() {
    extern __shared__ char smem[];
    const uint32_t sb = smem_u32(smem);
    const int t  = threadIdx.x;
    const int w  = t >> 5;
    const int l  = t & 31;
    const int mw = w >> 1;               // M-warp (64 rows each)
    const int nw = w & 1;                // N-warp (64 cols each)
    const int e0 = blockIdx.x * 128;
    const int n0 = blockIdx.y * 128;

    float acc[4][8][4];
    #pragma unroll
    for (int a = 0; a < 4; ++a)
        #pragma unroll
        for (int b = 0; b < 8; ++b)
            #pragma unroll
            for (int c = 0; c < 4; ++c) acc[a][b][c] = 0.f;

    uint32_t arow[4], amask[4];
    #pragma unroll
    for (int mt = 0; mt < 4; ++mt) {
        int row = mw * 64 + mt * 16 + (l & 15);
        arow[mt]  = (uint32_t)(row * 128);
        amask[mt] = (uint32_t)(row & 7);
    }
    const uint32_t ahi = (uint32_t)(l >> 4);
    uint32_t brow[4], bmask[4];
    #pragma unroll
    for (int p = 0; p < 4; ++p) {
        int row = nw * 64 + p * 16 + ((l >> 4) & 1) * 8 + (l & 7);
        brow[p]  = (uint32_t)(row * 128);
        bmask[p] = (uint32_t)(row & 7);
    }
    const uint32_t bhi = (uint32_t)((l >> 3) & 1);

    stage_issue(sb + 0 * STG, t, n0, e0, 0);
    stage_issue(sb + 1 * STG, t, n0, e0, KB);

    #pragma unroll
    for (int i = 0; i < NITER; ++i) {
        if (i != NITER - 1) asm volatile("cp.async.wait_group 1;" ::: "memory");
        else                asm volatile("cp.async.wait_group 0;" ::: "memory");
        __syncthreads();

        // early issue: buffer (i+2)%3 was consumed in iter i-1
        if (i + 2 < NITER)
            stage_issue(sb + (uint32_t)((i + 2) % 3) * STG, t, n0, e0, (i + 2) * KB);

        const uint32_t stA = sb + (uint32_t)(i % 3) * STG;
        const uint32_t stB = stA + TERMB;
        #pragma unroll
        for (int kk = 0; kk < 4; ++kk) {
            const uint32_t ch_a = (uint32_t)(kk * 2) + ahi;
            const uint32_t ch_b = (uint32_t)(kk * 2) + bhi;
            uint32_t Af[4][4], Bf[4][4];
            #pragma unroll
            for (int mt = 0; mt < 4; ++mt)
                ldsm4(Af[mt], stA + arow[mt] + ((ch_a ^ amask[mt]) << 4));
            #pragma unroll
            for (int p = 0; p < 4; ++p)
                ldsm4(Bf[p], stB + brow[p] + ((ch_b ^ bmask[p]) << 4));
            #pragma unroll
            for (int mt = 0; mt < 4; ++mt)
                #pragma unroll
                for (int nt = 0; nt < 8; ++nt) {
                    int p = nt >> 1, h = (nt & 1) * 2;
                    mma_f16(acc[mt][nt], Af[mt], Bf[p][h], Bf[p][h + 1]);
                }
        }
    }

    // ---- epilogue: store fp16 raw tile + fused BN partial sums --------------
    const int r0 = n0 + mw * 64;
    const int c0 = e0 + nw * 64;
    const int lr = l >> 2;
    const int lc = (l & 3) * 2;
    float cs[16], cq[16];
    #pragma unroll
    for (int j = 0; j < 16; ++j) { cs[j] = 0.f; cq[j] = 0.f; }

    #pragma unroll
    for (int mt = 0; mt < 4; ++mt)
        #pragma unroll
        for (int nt = 0; nt < 8; ++nt) {
            size_t o = (size_t)(r0 + mt * 16 + lr) * EDIM + c0 + nt * 8 + lc;
            float v0 = acc[mt][nt][0], v1 = acc[mt][nt][1];
            float v2 = acc[mt][nt][2], v3 = acc[mt][nt][3];
            *(__half2*)(g_raw + o)            = __floats2half2_rn(v0, v1);
            *(__half2*)(g_raw + o + 8 * EDIM) = __floats2half2_rn(v2, v3);
            cs[nt * 2 + 0] += v0 + v2;
            cs[nt * 2 + 1] += v1 + v3;
            cq[nt * 2 + 0] = fmaf(v0, v0, fmaf(v2, v2, cq[nt * 2 + 0]));
            cq[nt * 2 + 1] = fmaf(v1, v1, fmaf(v3, v3, cq[nt * 2 + 1]));
        }

    __syncthreads();                                   // smem stages now free
    float* red_s = (float*)smem;                       // [16][128]
    float* red_q = (float*)(smem + 8192);              // [16][128]
    const int tid16 = mw * 8 + lr;                     // 0..15
    #pragma unroll
    for (int nt = 0; nt < 8; ++nt) {
        int colc = nw * 64 + nt * 8 + lc;
        red_s[tid16 * 128 + colc]     = cs[nt * 2 + 0];
        red_s[tid16 * 128 + colc + 1] = cs[nt * 2 + 1];
        red_q[tid16 * 128 + colc]     = cq[nt * 2 + 0];
        red_q[tid16 * 128 + colc + 1] = cq[nt * 2 + 1];
    }
    __syncthreads();
    {
        float s = 0.f, q = 0.f;
        #pragma unroll
        for (int j = 0; j < 16; ++j) {
            s += red_s[j * 128 + t];
            q += red_q[j * 128 + t];
        }
        g_psum[(size_t)(e0 + t) * 512 + blockIdx.y] = s;
        g_psqs[(size_t)(e0 + t) * 512 + blockIdx.y] = q;
    }
}

// ---------------------------------------------------------------------------
// K3: bn_finalize — one warp per column.   [proven, 5.5us]
// ---------------------------------------------------------------------------
__global__ void __launch_bounds__(256) bn_finalize(const float* __restrict__ gamma,
                                                   const float* __restrict__ beta) {
    const int wid = threadIdx.x >> 5;
    const int l   = threadIdx.x & 31;
    const int c   = blockIdx.x * 8 + wid;          // 0..767
    const float* ps = g_psum + (size_t)c * 512;
    const float* pq = g_psqs + (size_t)c * 512;
    float s = 0.f, q = 0.f;
    #pragma unroll
    for (int j = 0; j < 16; ++j) {
        s += ps[l + 32 * j];
        q += pq[l + 32 * j];
    }
    #pragma unroll
    for (int d = 16; d > 0; d >>= 1) {
        s += __shfl_xor_sync(0xFFFFFFFF, s, d);
        q += __shfl_xor_sync(0xFFFFFFFF, q, d);
    }
    if (l == 0) {
        const float inv_n = 1.f / (float)NROWS;
        float mean = s * inv_n;
        float var  = q * inv_n - mean * mean;
        float rstd = rsqrtf(var + 1e-5f);
        float g = gamma[c] * rstd;
        g_scale[c] = g;
        g_shift[c] = beta[c] - mean * g;
    }
}

// ---------------------------------------------------------------------------
// K4: normalize + sigmoid.  Grid-stride float4; smem-cached scale/shift.
// ---------------------------------------------------------------------------
#define SIGBLK   1024
#define SIGTHR   256
#define NCHUNK4  (NROWS * (EDIM / 4))          // 12.58M float4-chunks

__global__ void __launch_bounds__(SIGTHR) bn_sigmoid(float* __restrict__ OUT) {
    __shared__ float s_sc[EDIM];
    __shared__ float s_sh[EDIM];
    for (int j = threadIdx.x; j < EDIM; j += SIGTHR) {
        s_sc[j] = g_scale[j];
        s_sh[j] = g_shift[j];
    }
    __syncthreads();

    int tid = blockIdx.x * SIGTHR + threadIdx.x;
    for (size_t c = tid; c < (size_t)NCHUNK4; c += (size_t)SIGBLK * SIGTHR) {
        int col4 = (int)(c % (EDIM / 4));          // 0..191
        uint2 rv = *(const uint2*)(g_raw + c * 4);
        __half2 h0 = *(__half2*)&rv.x;
        __half2 h1 = *(__half2*)&rv.y;
        float2 f0 = __half22float2(h0);
        float2 f1 = __half22float2(h1);
        float4 sc = ((const float4*)s_sc)[col4];
        float4 sh = ((const float4*)s_sh)[col4];
        float4 v;
        v.x = 1.f / (1.f + expf(-(fmaf(f0.x, sc.x, sh.x))));
        v.y = 1.f / (1.f + expf(-(fmaf(f0.y, sc.y, sh.y))));
        v.z = 1.f / (1.f + expf(-(fmaf(f1.x, sc.z, sh.z))));
        v.w = 1.f / (1.f + expf(-(fmaf(f1.y, sc.w, sh.w))));
        ((float4*)OUT)[c] = v;
    }
}

// ---------------------------------------------------------------------------
extern "C" void kernel_launch(void* const* d_in, const int* in_sizes, int n_in,
                              void* d_out, int out_size) {
    const float* x     = (const float*)d_in[0];
    const float* w1a   = (const float*)d_in[1];
    const float* w2a   = (const float*)d_in[2];
    const float* w1b   = (const float*)d_in[3];
    const float* w2b   = (const float*)d_in[4];
    const float* gamma = (const float*)d_in[5];
    const float* beta  = (const float*)d_in[6];
    float* out = (float*)d_out;

    cudaFuncSetAttribute(gemm_mma, cudaFuncAttributeMaxDynamicSharedMemorySize, SMEMB);

    prep_B_partial<<<dim3(EDIM / 64, 512 / 64, NSPLIT), 256>>>(w1a, w2a, w1b, w2b);
    prep_B_reduce<<<(KDIM * EDIM) / 256, 256>>>();
    conv_A<<<NROWS / 4, 256>>>(x);
    gemm_mma<<<dim3(EDIM / 128, NROWS / 128), 128, SMEMB>>>();
    bn_finalize<<<96, 256>>>(gamma, beta);
    bn_sigmoid<<<SIGBLK, SIGTHR>>>(out);
}

// round 16
// speedup vs baseline: 1.3189x; 1.3189x over previous
#include <cuda_runtime.h>
#include <cuda_bf16.h>
#include <cuda_fp16.h>
#include <cstdint>

// ---------------------------------------------------------------------------
// out = sigmoid(BN( A @ M )),  A (65536 x 512) fp16 built from x, M (512x768)
// pre-combined.  GEMM: fp16 mma.sync m16n8k16, CTA 128x128, 8 warps (2Mx4N),
// KB=64, 3-stage cp.async pipeline (unrolled, early issue), XOR-swizzled smem,
// BN partials fused in epilogue.  R15: gemm reverted to the proven R13 config
// (R14's 64x64 warp tile tanked occupancy: 242 regs, 8 warps/SM, HMMA
// degrades below 4 warps/SMSP); conv_A and prep_B_partial fused into one
// heterogeneous kernel so the FFMA-bound prep hides inside DRAM-bound conv_A.
// ---------------------------------------------------------------------------

#define NROWS   65536
#define DIN     768
#define KDIM    512
#define EDIM    768

#define KB      64          // K per stage
#define NITER   (KDIM / KB) // 8

#define TERMB   16384
#define STG     32768
#define SMEMB   (3 * STG)   // 98304

#define NSPLIT  4           // prep_B split-K factor
#define JCHUNK  (1536 / NSPLIT)

#define CONVBLK (NROWS / 4)             // 16384 conv blocks
#define PREPBLK (12 * 8 * NSPLIT)       // 384 prep blocks

// __device__ scratch (allocation-free rule)
__device__ __align__(16) float   g_Mp[NSPLIT * KDIM * EDIM];   // split-K partials
__device__ __align__(16) __half  g_Bf[EDIM * KDIM];            // [e][k]
__device__ __align__(16) __half  g_Af[(size_t)NROWS * KDIM];   // [n][k]
__device__ __align__(16) __half  g_raw[(size_t)NROWS * EDIM];  // fp16 raw out
__device__ __align__(16) float   g_psum[EDIM * 512];           // [col][rowblk]
__device__ __align__(16) float   g_psqs[EDIM * 512];
__device__ __align__(16) float   g_scale[EDIM];
__device__ __align__(16) float   g_shift[EDIM];

// ---------------- PTX helpers (baseline sm_80+ features only) ---------------
__device__ __forceinline__ uint32_t smem_u32(const void* p) {
    uint32_t a;
    asm("{ .reg .u64 t; cvta.to.shared.u64 t, %1; cvt.u32.u64 %0, t; }" : "=r"(a) : "l"(p));
    return a;
}
__device__ __forceinline__ void cp16(uint32_t dst, const void* src) {
    asm volatile("cp.async.cg.shared.global [%0], [%1], 16;" :: "r"(dst), "l"(src) : "memory");
}
__device__ __forceinline__ void ldsm4(uint32_t* r, uint32_t a) {
    asm volatile("ldmatrix.sync.aligned.m8n8.x4.shared.b16 {%0,%1,%2,%3}, [%4];"
                 : "=r"(r[0]), "=r"(r[1]), "=r"(r[2]), "=r"(r[3]) : "r"(a));
}
__device__ __forceinline__ void mma_f16(float* c, const uint32_t* a,
                                        uint32_t b0, uint32_t b1) {
    asm volatile(
        "mma.sync.aligned.m16n8k16.row.col.f32.f16.f16.f32 "
        "{%0,%1,%2,%3}, {%4,%5,%6,%7}, {%8,%9}, {%0,%1,%2,%3};"
        : "+f"(c[0]), "+f"(c[1]), "+f"(c[2]), "+f"(c[3])
        : "r"(a[0]), "r"(a[1]), "r"(a[2]), "r"(a[3]), "r"(b0), "r"(b1));
}

// ---------------------------------------------------------------------------
// K0: fused prep.  Blocks [0, CONVBLK): x -> g_Af (fp16, DRAM-bound).
//     Blocks [CONVBLK, CONVBLK+PREPBLK): split-K weight-prep partials
//     (FFMA-bound; hides inside the conv DRAM window).
// ---------------------------------------------------------------------------
__global__ void __launch_bounds__(256) prep_all(const float* __restrict__ X,
                                                const float* __restrict__ w1a,
                                                const float* __restrict__ w2a,
                                                const float* __restrict__ w1b,
                                                const float* __restrict__ w2b) {
    __shared__ __align__(16) float As[16][64];
    __shared__ __align__(16) float Bs[16][64];
    const int t = threadIdx.x;

    if (blockIdx.x < CONVBLK) {
        // ---- conv_A part: A(n,k) = x[n,0,k] (k<256) / x[n,1,..]+x[n,2,..] ----
        int id = blockIdx.x * 256 + t;
        int n  = id >> 6;
        int k  = (id & 63) * 8;
        const float* p = X + (size_t)n * DIN + k;
        float4 v0 = *(const float4*)p;
        float4 v1 = *(const float4*)(p + 4);
        if (k >= 256) {
            float4 w0 = *(const float4*)(p + 256);
            float4 w1 = *(const float4*)(p + 260);
            v0.x += w0.x; v0.y += w0.y; v0.z += w0.z; v0.w += w0.w;
            v1.x += w1.x; v1.y += w1.y; v1.z += w1.z; v1.w += w1.w;
        }
        __half2 h0 = __float22half2_rn(make_float2(v0.x, v0.y));
        __half2 h1 = __float22half2_rn(make_float2(v0.z, v0.w));
        __half2 h2 = __float22half2_rn(make_float2(v1.x, v1.y));
        __half2 h3 = __float22half2_rn(make_float2(v1.z, v1.w));
        uint4 o;
        o.x = *(uint32_t*)&h0; o.y = *(uint32_t*)&h1;
        o.z = *(uint32_t*)&h2; o.w = *(uint32_t*)&h3;
        *(uint4*)(g_Af + (size_t)n * KDIM + k) = o;
        return;
    }

    // ---- prep_B_partial part: 64x64 tile of split-K z-slice ----
    const int b  = blockIdx.x - CONVBLK;            // 0..383
    const int e0 = (b % 12) * 64;
    const int i0 = ((b / 12) & 7) * 64;
    const int jz = (b / 96) * JCHUNK;
    const int tx = t & 15;
    const int ty = t >> 4;
    float acc[4][4] = {};

    for (int j0 = jz; j0 < jz + JCHUNK; j0 += 16) {
        {   // A tile: L(i0+r, j0+jq..+3) computed on the fly
            int r  = t >> 2;
            int jq = (t & 3) * 4;
            int i  = i0 + r;
            int j  = j0 + jq;
            float4 v;
            if (j < 768) {
                if (i < 256) {
                    v = *(const float4*)&w2a[(size_t)i * 768 + j];
                } else {
                    float4 a = *(const float4*)&w1a[(size_t)(i - 256) * 768 + j];
                    v = make_float4(0.5f * a.x, 0.5f * a.y, 0.5f * a.z, 0.5f * a.w);
                }
            } else {
                int jj = j - 768;
                if (i < 256) {
                    float4 a = *(const float4*)&w1a[(size_t)i * 768 + jj];
                    v = make_float4(0.5f * a.x, 0.5f * a.y, 0.5f * a.z, 0.5f * a.w);
                } else {
                    float4 a = *(const float4*)&w2a[(size_t)(i - 256) * 768 + jj];
                    float4 bb = *(const float4*)&w1a[(size_t)(i - 256) * 768 + jj];
                    v = make_float4(fmaf(0.25f, bb.x, 0.5f * a.x),
                                    fmaf(0.25f, bb.y, 0.5f * a.y),
                                    fmaf(0.25f, bb.z, 0.5f * a.z),
                                    fmaf(0.25f, bb.w, 0.5f * a.w));
                }
            }
            As[jq + 0][r] = v.x; As[jq + 1][r] = v.y;
            As[jq + 2][r] = v.z; As[jq + 3][r] = v.w;
        }
        {   // B tile: [w2b ; w1b](j0+k, e0+eq..)
            int k  = t >> 4;
            int eq = (t & 15) * 4;
            int j  = j0 + k;
            const float* src = (j < 768) ? (w2b + (size_t)j * 768)
                                         : (w1b + (size_t)(j - 768) * 768);
            *(float4*)&Bs[k][eq] = *(const float4*)(src + e0 + eq);
        }
        __syncthreads();
        #pragma unroll
        for (int k = 0; k < 16; ++k) {
            float4 a = *(const float4*)&As[k][ty * 4];
            float4 bv4 = *(const float4*)&Bs[k][tx * 4];
            float av[4] = {a.x, a.y, a.z, a.w};
            float bv[4] = {bv4.x, bv4.y, bv4.z, bv4.w};
            #pragma unroll
            for (int i = 0; i < 4; ++i)
                #pragma unroll
                for (int j = 0; j < 4; ++j)
                    acc[i][j] = fmaf(av[i], bv[j], acc[i][j]);
        }
        __syncthreads();
    }
    float* dst = g_Mp + (size_t)(b / 96) * KDIM * EDIM;
    #pragma unroll
    for (int i = 0; i < 4; ++i)
        *(float4*)&dst[(size_t)(i0 + ty * 4 + i) * EDIM + e0 + tx * 4] =
            make_float4(acc[i][0], acc[i][1], acc[i][2], acc[i][3]);
}

// ---------------------------------------------------------------------------
// K0b: reduce split-K partials -> g_Bf = fp16(M^T)   [proven]
// ---------------------------------------------------------------------------
__global__ void __launch_bounds__(256) prep_B_reduce() {
    int idx = blockIdx.x * 256 + threadIdx.x;        // 512*768
    int k = idx / EDIM;
    int e = idx % EDIM;
    float s = g_Mp[idx];
    #pragma unroll
    for (int z = 1; z < NSPLIT; ++z)
        s += g_Mp[(size_t)z * KDIM * EDIM + idx];
    g_Bf[(size_t)e * KDIM + k] = __float2half_rn(s);
}

// ---------------------------------------------------------------------------
// K1: main GEMM via fp16 mma.sync + fused BN partials.  grid (6, 512),
// 256 threads, 8 warps 2Mx4N (warp 64x32), 2 CTAs/SM.   [R13 proven, 144us]
// ---------------------------------------------------------------------------
__device__ __forceinline__ void stage_issue(uint32_t st, int t, int n0, int e0, int k0) {
    #pragma unroll
    for (int j = 0; j < 8; ++j) {
        int idx  = t + 256 * j;          // 0..2047
        int part = idx >> 10;            // 0: A, 1: B
        int rr   = (idx >> 3) & 127;
        int c    = idx & 7;
        uint32_t dst = st + (uint32_t)(part * TERMB + rr * 128 + ((c ^ (rr & 7)) << 4));
        const __half* g = part ? g_Bf : g_Af;
        int base = part ? e0 : n0;
        cp16(dst, g + (size_t)(base + rr) * KDIM + k0 + c * 8);
    }
    asm volatile("cp.async.commit_group;" ::: "memory");
}

__global__ void __launch_bounds__(256, 2) gemm_mma() {
    extern __shared__ char smem[];
    const uint32_t sb = smem_u32(smem);
    const int t  = threadIdx.x;
    const int w  = t >> 5;
    const int l  = t & 31;
    const int mw = w & 1;                // M-warp (64 rows each)
    const int nw = w >> 1;               // N-warp (32 cols each)
    const int e0 = blockIdx.x * 128;
    const int n0 = blockIdx.y * 128;

    float acc[4][4][4];
    #pragma unroll
    for (int a = 0; a < 4; ++a)
        #pragma unroll
        for (int b = 0; b < 4; ++b)
            #pragma unroll
            for (int c = 0; c < 4; ++c) acc[a][b][c] = 0.f;

    uint32_t arow[4], amask[4];
    #pragma unroll
    for (int mt = 0; mt < 4; ++mt) {
        int row = mw * 64 + mt * 16 + (l & 15);
        arow[mt]  = (uint32_t)(row * 128);
        amask[mt] = (uint32_t)(row & 7);
    }
    const uint32_t ahi = (uint32_t)(l >> 4);
    uint32_t brow[2], bmask[2];
    #pragma unroll
    for (int p = 0; p < 2; ++p) {
        int row = nw * 32 + p * 16 + ((l >> 4) & 1) * 8 + (l & 7);
        brow[p]  = (uint32_t)(row * 128);
        bmask[p] = (uint32_t)(row & 7);
    }
    const uint32_t bhi = (uint32_t)((l >> 3) & 1);

    stage_issue(sb + 0 * STG, t, n0, e0, 0);
    stage_issue(sb + 1 * STG, t, n0, e0, KB);

    #pragma unroll
    for (int i = 0; i < NITER; ++i) {
        if (i != NITER - 1) asm volatile("cp.async.wait_group 1;" ::: "memory");
        else                asm volatile("cp.async.wait_group 0;" ::: "memory");
        __syncthreads();

        // early issue: buffer (i+2)%3 was consumed in iter i-1
        if (i + 2 < NITER)
            stage_issue(sb + (uint32_t)((i + 2) % 3) * STG, t, n0, e0, (i + 2) * KB);

        const uint32_t stA = sb + (uint32_t)(i % 3) * STG;
        const uint32_t stB = stA + TERMB;
        #pragma unroll
        for (int kk = 0; kk < 4; ++kk) {
            const uint32_t ch_a = (uint32_t)(kk * 2) + ahi;
            const uint32_t ch_b = (uint32_t)(kk * 2) + bhi;
            uint32_t Af[4][4], Bf[2][4];
            #pragma unroll
            for (int mt = 0; mt < 4; ++mt)
                ldsm4(Af[mt], stA + arow[mt] + ((ch_a ^ amask[mt]) << 4));
            #pragma unroll
            for (int p = 0; p < 2; ++p)
                ldsm4(Bf[p], stB + brow[p] + ((ch_b ^ bmask[p]) << 4));
            #pragma unroll
            for (int mt = 0; mt < 4; ++mt)
                #pragma unroll
                for (int nt = 0; nt < 4; ++nt) {
                    int p = nt >> 1, h = (nt & 1) * 2;
                    mma_f16(acc[mt][nt], Af[mt], Bf[p][h], Bf[p][h + 1]);
                }
        }
    }

    // ---- epilogue: store fp16 raw tile + fused BN partial sums --------------
    const int r0 = n0 + mw * 64;
    const int c0 = e0 + nw * 32;
    const int lr = l >> 2;
    const int lc = (l & 3) * 2;
    float cs[8], cq[8];
    #pragma unroll
    for (int j = 0; j < 8; ++j) { cs[j] = 0.f; cq[j] = 0.f; }

    #pragma unroll
    for (int mt = 0; mt < 4; ++mt)
        #pragma unroll
        for (int nt = 0; nt < 4; ++nt) {
            size_t o = (size_t)(r0 + mt * 16 + lr) * EDIM + c0 + nt * 8 + lc;
            float v0 = acc[mt][nt][0], v1 = acc[mt][nt][1];
            float v2 = acc[mt][nt][2], v3 = acc[mt][nt][3];
            *(__half2*)(g_raw + o)            = __floats2half2_rn(v0, v1);
            *(__half2*)(g_raw + o + 8 * EDIM) = __floats2half2_rn(v2, v3);
            cs[nt * 2 + 0] += v0 + v2;
            cs[nt * 2 + 1] += v1 + v3;
            cq[nt * 2 + 0] = fmaf(v0, v0, fmaf(v2, v2, cq[nt * 2 + 0]));
            cq[nt * 2 + 1] = fmaf(v1, v1, fmaf(v3, v3, cq[nt * 2 + 1]));
        }

    __syncthreads();                                   // smem stages now free
    float* red_s = (float*)smem;                       // [16][128]
    float* red_q = (float*)(smem + 8192);              // [16][128]
    const int tid16 = mw * 8 + lr;                     // 0..15
    #pragma unroll
    for (int nt = 0; nt < 4; ++nt) {
        int colc = nw * 32 + nt * 8 + lc;
        red_s[tid16 * 128 + colc]     = cs[nt * 2 + 0];
        red_s[tid16 * 128 + colc + 1] = cs[nt * 2 + 1];
        red_q[tid16 * 128 + colc]     = cq[nt * 2 + 0];
        red_q[tid16 * 128 + colc + 1] = cq[nt * 2 + 1];
    }
    __syncthreads();
    if (t < 128) {
        float s = 0.f, q = 0.f;
        #pragma unroll
        for (int j = 0; j < 16; ++j) {
            s += red_s[j * 128 + t];
            q += red_q[j * 128 + t];
        }
        g_psum[(size_t)(e0 + t) * 512 + blockIdx.y] = s;
        g_psqs[(size_t)(e0 + t) * 512 + blockIdx.y] = q;
    }
}

// ---------------------------------------------------------------------------
// K2: bn_finalize — one warp per column.   [proven, 5.5us]
// ---------------------------------------------------------------------------
__global__ void __launch_bounds__(256) bn_finalize(const float* __restrict__ gamma,
                                                   const float* __restrict__ beta) {
    const int wid = threadIdx.x >> 5;
    const int l   = threadIdx.x & 31;
    const int c   = blockIdx.x * 8 + wid;          // 0..767
    const float* ps = g_psum + (size_t)c * 512;
    const float* pq = g_psqs + (size_t)c * 512;
    float s = 0.f, q = 0.f;
    #pragma unroll
    for (int j = 0; j < 16; ++j) {
        s += ps[l + 32 * j];
        q += pq[l + 32 * j];
    }
    #pragma unroll
    for (int d = 16; d > 0; d >>= 1) {
        s += __shfl_xor_sync(0xFFFFFFFF, s, d);
        q += __shfl_xor_sync(0xFFFFFFFF, q, d);
    }
    if (l == 0) {
        const float inv_n = 1.f / (float)NROWS;
        float mean = s * inv_n;
        float var  = q * inv_n - mean * mean;
        float rstd = rsqrtf(var + 1e-5f);
        float g = gamma[c] * rstd;
        g_scale[c] = g;
        g_shift[c] = beta[c] - mean * g;
    }
}

// ---------------------------------------------------------------------------
// K3: normalize + sigmoid.  Grid-stride float4; smem-cached scale/shift.
// ---------------------------------------------------------------------------
#define SIGBLK   1024
#define SIGTHR   256
#define NCHUNK4  (NROWS * (EDIM / 4))          // 12.58M float4-chunks

__global__ void __launch_bounds__(SIGTHR) bn_sigmoid(float* __restrict__ OUT) {
    __shared__ float s_sc[EDIM];
    __shared__ float s_sh[EDIM];
    for (int j = threadIdx.x; j < EDIM; j += SIGTHR) {
        s_sc[j] = g_scale[j];
        s_sh[j] = g_shift[j];
    }
    __syncthreads();

    int tid = blockIdx.x * SIGTHR + threadIdx.x;
    for (size_t c = tid; c < (size_t)NCHUNK4; c += (size_t)SIGBLK * SIGTHR) {
        int col4 = (int)(c % (EDIM / 4));          // 0..191
        uint2 rv = *(const uint2*)(g_raw + c * 4);
        __half2 h0 = *(__half2*)&rv.x;
        __half2 h1 = *(__half2*)&rv.y;
        float2 f0 = __half22float2(h0);
        float2 f1 = __half22float2(h1);
        float4 sc = ((const float4*)s_sc)[col4];
        float4 sh = ((const float4*)s_sh)[col4];
        float4 v;
        v.x = 1.f / (1.f + expf(-(fmaf(f0.x, sc.x, sh.x))));
        v.y = 1.f / (1.f + expf(-(fmaf(f0.y, sc.y, sh.y))));
        v.z = 1.f / (1.f + expf(-(fmaf(f1.x, sc.z, sh.z))));
        v.w = 1.f / (1.f + expf(-(fmaf(f1.y, sc.w, sh.w))));
        ((float4*)OUT)[c] = v;
    }
}

// ---------------------------------------------------------------------------
extern "C" void kernel_launch(void* const* d_in, const int* in_sizes, int n_in,
                              void* d_out, int out_size) {
    const float* x     = (const float*)d_in[0];
    const float* w1a   = (const float*)d_in[1];
    const float* w2a   = (const float*)d_in[2];
    const float* w1b   = (const float*)d_in[3];
    const float* w2b   = (const float*)d_in[4];
    const float* gamma = (const float*)d_in[5];
    const float* beta  = (const float*)d_in[6];
    float* out = (float*)d_out;

    cudaFuncSetAttribute(gemm_mma, cudaFuncAttributeMaxDynamicSharedMemorySize, SMEMB);

    prep_all<<<CONVBLK + PREPBLK, 256>>>(x, w1a, w2a, w1b, w2b);
    prep_B_reduce<<<(KDIM * EDIM) / 256, 256>>>();
    gemm_mma<<<dim3(EDIM / 128, NROWS / 128), 256, SMEMB>>>();
    bn_finalize<<<96, 256>>>(gamma, beta);
    bn_sigmoid<<<SIGBLK, SIGTHR>>>(out);
}